// round 1
// baseline (speedup 1.0000x reference)
#include <cuda_runtime.h>
#include <cstdint>

#define D 128
#define MAXN 100000

// ---------------- scratch (allocation-free: device globals) ----------------
__device__ float g_stats[2 * D];              // [0:128) col sums, [128:256) col sumsq
__device__ float g_ab[2 * D];                 // [0:128) scale a, [128:256) bias b
__device__ float g_Wt[D * D];                 // W transposed: g_Wt[k*128+n] = W[n*128+k]
__device__ float g_h[(size_t)MAXN * D];       // h = relu(bn(x)) @ W^T   (51.2 MB)

// ---------------- f32x2 packed-FMA helpers (sm_100+) ----------------
__device__ __forceinline__ unsigned long long pack2(float x) {
    unsigned long long r;
    asm("mov.b64 %0, {%1, %1};" : "=l"(r) : "f"(x));
    return r;
}
__device__ __forceinline__ void ffma2(unsigned long long& d, unsigned long long a, unsigned long long b) {
    asm("fma.rn.f32x2 %0, %1, %2, %0;" : "+l"(d) : "l"(a), "l"(b));
}
__device__ __forceinline__ float2 unpack2(unsigned long long v) {
    float2 r;
    asm("mov.b64 {%0, %1}, %2;" : "=f"(r.x), "=f"(r.y) : "l"(v));
    return r;
}

// ---------------- k0: zero stats scratch + transpose W ----------------
__global__ void k0_prep(const float* __restrict__ W) {
    int i = blockIdx.x * 256 + threadIdx.x;
    if (i < 2 * D) g_stats[i] = 0.0f;
    if (i < D * D) {
        int n = i >> 7;       // output row of W
        int k = i & 127;      // input col of W
        g_Wt[k * D + n] = W[i];   // coalesced read, scattered write (one-time, 64KB)
    }
}

// ---------------- k1: column mean / mean-of-squares partials ----------------
__global__ void __launch_bounds__(256) k1_stats(const float4* __restrict__ x4, int nrows) {
    int tx = threadIdx.x & 31;   // column quad: cols 4*tx .. 4*tx+3
    int ty = threadIdx.x >> 5;   // row lane within block (8 warps)
    float4 s = {0.f, 0.f, 0.f, 0.f};
    float4 q = {0.f, 0.f, 0.f, 0.f};
    for (int r = blockIdx.x * 8 + ty; r < nrows; r += gridDim.x * 8) {
        float4 v = x4[(size_t)r * 32 + tx];
        s.x += v.x; s.y += v.y; s.z += v.z; s.w += v.w;
        q.x += v.x * v.x; q.y += v.y * v.y; q.z += v.z * v.z; q.w += v.w * v.w;
    }
    // block-level reduce across the 8 warps, then one atomic set per column quad
    __shared__ float4 red_s[8][32];
    __shared__ float4 red_q[8][32];
    red_s[ty][tx] = s;
    red_q[ty][tx] = q;
    __syncthreads();
    if (ty == 0) {
        for (int w = 1; w < 8; w++) {
            float4 a = red_s[w][tx], b = red_q[w][tx];
            s.x += a.x; s.y += a.y; s.z += a.z; s.w += a.w;
            q.x += b.x; q.y += b.y; q.z += b.z; q.w += b.w;
        }
        atomicAdd(&g_stats[4 * tx + 0], s.x);
        atomicAdd(&g_stats[4 * tx + 1], s.y);
        atomicAdd(&g_stats[4 * tx + 2], s.z);
        atomicAdd(&g_stats[4 * tx + 3], s.w);
        atomicAdd(&g_stats[D + 4 * tx + 0], q.x);
        atomicAdd(&g_stats[D + 4 * tx + 1], q.y);
        atomicAdd(&g_stats[D + 4 * tx + 2], q.z);
        atomicAdd(&g_stats[D + 4 * tx + 3], q.w);
    }
}

// ---------------- k2: finalize BN affine:  y = a*x + b  ----------------
__global__ void k2_final(const float* __restrict__ gamma, const float* __restrict__ beta, float inv_n) {
    int c = threadIdx.x;
    float mu  = g_stats[c] * inv_n;
    float var = fmaxf(g_stats[D + c] * inv_n - mu * mu, 0.0f);
    float inv = rsqrtf(var + 1e-5f);
    float a = gamma[c] * inv;
    g_ab[c]     = a;
    g_ab[D + c] = beta[c] - mu * a;
}

// ---------------- k3: fused BN+ReLU+GEMM(+h*h epilogue) ----------------
// 64 rows per block, 256 threads, f32x2 packed FMAs (2 cols per 64-bit acc).
// smem: Wt (K-major, 64KB) + Xs (normalized tile, 32KB) = 96KB -> 2 blocks/SM.
__global__ void __launch_bounds__(256, 2) k3_gemm(const float* __restrict__ x,
                                                  float* __restrict__ out, int nrows) {
    extern __shared__ float sm[];
    float* Wt = sm;             // [128][128], Wt[k*128+n]
    float* Xs = sm + D * D;     // [64][128]
    int tid = threadIdx.x;
    int tx = tid & 31;          // col quad: 4*tx .. 4*tx+3
    int ty = tid >> 5;          // row group: rows ty*8 .. ty*8+7

    // load Wt (coalesced, conflict-free)
    {
        float4* Wt4 = (float4*)Wt;
        const float4* gWt4 = (const float4*)g_Wt;
        #pragma unroll
        for (int it = 0; it < 16; it++) Wt4[tid + it * 256] = gWt4[tid + it * 256];
    }
    // load + normalize X tile
    {
        int row0 = blockIdx.x * 64;
        const float4* x4 = (const float4*)x;
        const float4* ab4 = (const float4*)g_ab;
        float4* Xs4 = (float4*)Xs;
        #pragma unroll
        for (int it = 0; it < 8; it++) {
            int i = tid + it * 256;       // 0..2047 over [64 rows][32 quads]
            int r = i >> 5, kq = i & 31;
            float4 v = {0.f, 0.f, 0.f, 0.f};
            if (row0 + r < nrows) v = x4[(size_t)(row0 + r) * 32 + kq];
            float4 a = ab4[kq], b = ab4[32 + kq];
            float4 y;
            y.x = fmaxf(fmaf(a.x, v.x, b.x), 0.f);
            y.y = fmaxf(fmaf(a.y, v.y, b.y), 0.f);
            y.z = fmaxf(fmaf(a.z, v.z, b.z), 0.f);
            y.w = fmaxf(fmaf(a.w, v.w, b.w), 0.f);
            Xs4[i] = y;
        }
    }
    __syncthreads();

    unsigned long long acc[8][2];
    #pragma unroll
    for (int i = 0; i < 8; i++) { acc[i][0] = 0ull; acc[i][1] = 0ull; }

    const float4* Xs4 = (const float4*)Xs;
    #pragma unroll 2
    for (int kq = 0; kq < 32; kq++) {
        ulonglong2 w[4];
        #pragma unroll
        for (int j = 0; j < 4; j++)
            w[j] = *(const ulonglong2*)(&Wt[(4 * kq + j) * D + 4 * tx]);  // 2 col-pairs
        #pragma unroll
        for (int i = 0; i < 8; i++) {
            float4 xq = Xs4[(ty * 8 + i) * 32 + kq];   // broadcast within warp
            unsigned long long xp;
            xp = pack2(xq.x); ffma2(acc[i][0], xp, w[0].x); ffma2(acc[i][1], xp, w[0].y);
            xp = pack2(xq.y); ffma2(acc[i][0], xp, w[1].x); ffma2(acc[i][1], xp, w[1].y);
            xp = pack2(xq.z); ffma2(acc[i][0], xp, w[2].x); ffma2(acc[i][1], xp, w[2].y);
            xp = pack2(xq.w); ffma2(acc[i][0], xp, w[3].x); ffma2(acc[i][1], xp, w[3].y);
        }
    }

    // epilogue: h -> g_h, out = h*h (initializes the output for the edge pass)
    int row0 = blockIdx.x * 64;
    #pragma unroll
    for (int i = 0; i < 8; i++) {
        int row = row0 + ty * 8 + i;
        if (row < nrows) {
            float2 p0 = unpack2(acc[i][0]);
            float2 p1 = unpack2(acc[i][1]);
            float4 hv = {p0.x, p0.y, p1.x, p1.y};
            size_t off = (size_t)row * 32 + tx;
            ((float4*)g_h)[off] = hv;
            float4 sq = {hv.x * hv.x, hv.y * hv.y, hv.z * hv.z, hv.w * hv.w};
            ((float4*)out)[off] = sq;
        }
    }
}

// ---------------- k4: edge gather + vector-red scatter ----------------
// one warp per edge: 1 LDG.128 gather + 1 RED.128 scatter per lane.
__global__ void __launch_bounds__(256) k4_edge(const int* __restrict__ ei,
                                               const float* __restrict__ ew,
                                               float* __restrict__ out, int E) {
    int gw = (blockIdx.x * 256 + threadIdx.x) >> 5;
    if (gw >= E) return;
    int lane = threadIdx.x & 31;
    int row = __ldg(&ei[gw]);
    int col = __ldg(&ei[E + gw]);
    float w = __ldg(&ew[gw]);
    float4 v = ((const float4*)g_h)[(size_t)col * 32 + lane];
    float* dst = out + (size_t)row * D + lane * 4;
    asm volatile("red.global.add.v4.f32 [%0], {%1, %2, %3, %4};"
                 :: "l"(dst), "f"(v.x * w), "f"(v.y * w), "f"(v.z * w), "f"(v.w * w)
                 : "memory");
}

// ---------------- launch ----------------
extern "C" void kernel_launch(void* const* d_in, const int* in_sizes, int n_in,
                              void* d_out, int out_size) {
    const float* n_feat = (const float*)d_in[0];
    const int*   ei     = (const int*)d_in[1];
    const float* ew     = (const float*)d_in[2];
    const float* gamma  = (const float*)d_in[3];
    const float* beta   = (const float*)d_in[4];
    const float* W      = (const float*)d_in[5];
    float* out = (float*)d_out;

    int N = in_sizes[0] / D;
    int E = in_sizes[2];

    k0_prep<<<(D * D + 255) / 256, 256>>>(W);
    k1_stats<<<264, 256>>>((const float4*)n_feat, N);
    k2_final<<<1, D>>>(gamma, beta, 1.0f / (float)N);

    cudaFuncSetAttribute(k3_gemm, cudaFuncAttributeMaxDynamicSharedMemorySize, (D * D + 64 * D) * 4);
    k3_gemm<<<(N + 63) / 64, 256, (D * D + 64 * D) * 4>>>(n_feat, out, N);

    k4_edge<<<(E + 7) / 8, 256>>>(ei, ew, out, E);
}

// round 3
// speedup vs baseline: 1.1435x; 1.1435x over previous
#include <cuda_runtime.h>
#include <cuda_bf16.h>
#include <cstdint>

#define D 128
#define MAXN 100000
#define MAXE 400000
#define TILE_M 128
#define NSCAN 391            // (MAXN+255)/256

// ---------------- scratch (allocation-free: device globals) ----------------
__device__ float g_stats[2 * D];                    // col sums / sumsq
__device__ float g_ab[2 * D];                       // BN affine a / b
__device__ unsigned short g_Whi[D * 136];           // bf16 hi, padded [n][k] stride 136
__device__ unsigned short g_Wlo[D * 136];           // bf16 lo
__device__ float g_h[(size_t)MAXN * D];             // h (51.2 MB)
__device__ int   g_deg[MAXN];
__device__ int   g_off[MAXN + 1];
__device__ int   g_cur[MAXN];
__device__ int   g_bsum[NSCAN];
__device__ int   g_bbase[NSCAN];
__device__ int   g_ecol[MAXE];
__device__ float g_ewt[MAXE];

// ---------------- helpers ----------------
__device__ __forceinline__ uint32_t smem_u32(const void* p) {
    uint32_t a;
    asm("{ .reg .u64 t; cvta.to.shared.u64 t, %1; cvt.u32.u64 %0, t; }" : "=r"(a) : "l"(p));
    return a;
}
__device__ __forceinline__ void ldmx4(uint32_t addr, uint32_t r[4]) {
    asm volatile("ldmatrix.sync.aligned.m8n8.x4.shared.b16 {%0,%1,%2,%3}, [%4];"
                 : "=r"(r[0]), "=r"(r[1]), "=r"(r[2]), "=r"(r[3]) : "r"(addr));
}
__device__ __forceinline__ void mma16816(float c[4], const uint32_t a[4], const uint32_t b[2]) {
    asm volatile("mma.sync.aligned.m16n8k16.row.col.f32.bf16.bf16.f32 "
                 "{%0,%1,%2,%3}, {%4,%5,%6,%7}, {%8,%9}, {%0,%1,%2,%3};"
                 : "+f"(c[0]), "+f"(c[1]), "+f"(c[2]), "+f"(c[3])
                 : "r"(a[0]), "r"(a[1]), "r"(a[2]), "r"(a[3]), "r"(b[0]), "r"(b[1]));
}
__device__ __forceinline__ uint32_t pkbf2(float x, float y) {
    __nv_bfloat162 t = __floats2bfloat162_rn(x, y);
    return *(uint32_t*)&t;
}

// ---------------- k0: zero stats+deg, build padded W bf16 hi/lo ----------------
__global__ void k0_prep(const float* __restrict__ W) {
    int i = blockIdx.x * 256 + threadIdx.x;
    if (i < 2 * D) g_stats[i] = 0.0f;
    if (i < MAXN) g_deg[i] = 0;
    if (i < D * D) {
        int n = i >> 7, k = i & 127;
        float w = W[i];
        __nv_bfloat16 hi = __float2bfloat16(w);
        float lf = w - __bfloat162float(hi);
        g_Whi[n * 136 + k] = __bfloat16_as_ushort(hi);
        g_Wlo[n * 136 + k] = __bfloat16_as_ushort(__float2bfloat16(lf));
    }
}

// ---------------- k1: column sums / sumsq ----------------
__global__ void __launch_bounds__(256) k1_stats(const float4* __restrict__ x4, int nrows) {
    int tx = threadIdx.x & 31, ty = threadIdx.x >> 5;
    float4 s = {0.f, 0.f, 0.f, 0.f}, q = {0.f, 0.f, 0.f, 0.f};
    for (int r = blockIdx.x * 8 + ty; r < nrows; r += gridDim.x * 8) {
        float4 v = x4[(size_t)r * 32 + tx];
        s.x += v.x; s.y += v.y; s.z += v.z; s.w += v.w;
        q.x += v.x * v.x; q.y += v.y * v.y; q.z += v.z * v.z; q.w += v.w * v.w;
    }
    __shared__ float4 rs[8][32], rq[8][32];
    rs[ty][tx] = s; rq[ty][tx] = q;
    __syncthreads();
    if (ty == 0) {
        for (int w = 1; w < 8; w++) {
            float4 a = rs[w][tx], b = rq[w][tx];
            s.x += a.x; s.y += a.y; s.z += a.z; s.w += a.w;
            q.x += b.x; q.y += b.y; q.z += b.z; q.w += b.w;
        }
        atomicAdd(&g_stats[4 * tx + 0], s.x);
        atomicAdd(&g_stats[4 * tx + 1], s.y);
        atomicAdd(&g_stats[4 * tx + 2], s.z);
        atomicAdd(&g_stats[4 * tx + 3], s.w);
        atomicAdd(&g_stats[D + 4 * tx + 0], q.x);
        atomicAdd(&g_stats[D + 4 * tx + 1], q.y);
        atomicAdd(&g_stats[D + 4 * tx + 2], q.z);
        atomicAdd(&g_stats[D + 4 * tx + 3], q.w);
    }
}

// ---------------- k2: finalize BN affine ----------------
__global__ void k2_final(const float* __restrict__ gamma, const float* __restrict__ beta, float inv_n) {
    int c = threadIdx.x;
    float mu  = g_stats[c] * inv_n;
    float var = fmaxf(g_stats[D + c] * inv_n - mu * mu, 0.0f);
    float a = gamma[c] * rsqrtf(var + 1e-5f);
    g_ab[c] = a;
    g_ab[D + c] = beta[c] - mu * a;
}

// ---------------- k3: HMMA bf16 2-split GEMM ----------------
// smem: Whi | Wlo | Xhi | Xlo, each 128 rows x 136 bf16 (34816B). Total 139264B.
#define SM_WHI 0
#define SM_WLO 34816
#define SM_XHI 69632
#define SM_XLO 104448
#define SM_TOTAL 139264
#define XSTR 272     // row stride bytes

__global__ void __launch_bounds__(256, 1) k3_mma(const float* __restrict__ x,
                                                 int nrows, int ntiles) {
    extern __shared__ __align__(16) char sm[];
    uint32_t smb = smem_u32(sm);
    int tid = threadIdx.x, wid = tid >> 5, lane = tid & 31;
    int warp_m = wid & 3;       // 4 m-blocks of 32 rows
    int warp_n = wid >> 2;      // 2 n-blocks of 64 cols

    // copy W hi/lo (padded layout) into smem
    {
        const uint4* hs = (const uint4*)g_Whi;
        const uint4* ls = (const uint4*)g_Wlo;
        uint4* hd = (uint4*)(sm + SM_WHI);
        uint4* ld = (uint4*)(sm + SM_WLO);
        for (int i = tid; i < 2176; i += 256) { hd[i] = hs[i]; ld[i] = ls[i]; }
    }

    // lane-pattern offsets for ldmatrix
    int laneRowA = (lane & 7) + ((lane >> 3) & 1) * 8;
    int laneKA   = (lane >> 4) * 8;
    int laneRowB = (lane & 7) + ((lane >> 4) & 1) * 8;
    int laneKB   = ((lane >> 3) & 1) * 8;
    uint32_t aoff = (uint32_t)((warp_m * 32 + laneRowA) * XSTR + laneKA * 2);
    uint32_t boff = (uint32_t)((warp_n * 64 + laneRowB) * XSTR + laneKB * 2);
    uint32_t a_hi = smb + SM_XHI + aoff, a_lo = smb + SM_XLO + aoff;
    uint32_t b_hi = smb + SM_WHI + boff, b_lo = smb + SM_WLO + boff;

    const float4* x4 = (const float4*)x;
    const float4* ab4 = (const float4*)g_ab;

    for (int t = blockIdx.x; t < ntiles; t += gridDim.x) {
        // ---- stage X tile: normalize -> relu -> bf16 hi/lo ----
        __syncthreads();
        #pragma unroll
        for (int it = 0; it < 16; it++) {
            int ci = tid + it * 256;          // 0..4095 over [128 rows][32 quads]
            int r = ci >> 5, cq = ci & 31;
            int gr = t * TILE_M + r;
            float4 v = {0.f, 0.f, 0.f, 0.f};
            if (gr < nrows) v = x4[(size_t)gr * 32 + cq];
            float4 a = __ldg(&ab4[cq]), b = __ldg(&ab4[32 + cq]);
            float y0 = fmaxf(fmaf(a.x, v.x, b.x), 0.f);
            float y1 = fmaxf(fmaf(a.y, v.y, b.y), 0.f);
            float y2 = fmaxf(fmaf(a.z, v.z, b.z), 0.f);
            float y3 = fmaxf(fmaf(a.w, v.w, b.w), 0.f);
            __nv_bfloat16 h0 = __float2bfloat16(y0), h1 = __float2bfloat16(y1);
            __nv_bfloat16 h2 = __float2bfloat16(y2), h3 = __float2bfloat16(y3);
            uint2 hiw, low;
            hiw.x = (uint32_t)__bfloat16_as_ushort(h0) | ((uint32_t)__bfloat16_as_ushort(h1) << 16);
            hiw.y = (uint32_t)__bfloat16_as_ushort(h2) | ((uint32_t)__bfloat16_as_ushort(h3) << 16);
            low.x = pkbf2(y0 - __bfloat162float(h0), y1 - __bfloat162float(h1));
            low.y = pkbf2(y2 - __bfloat162float(h2), y3 - __bfloat162float(h3));
            uint32_t off = (uint32_t)(r * XSTR + cq * 8);
            *(uint2*)(sm + SM_XHI + off) = hiw;
            *(uint2*)(sm + SM_XLO + off) = low;
        }
        __syncthreads();

        // ---- mainloop: 8 k16-steps x 3 products ----
        float acc[2][8][4];
        #pragma unroll
        for (int mt = 0; mt < 2; mt++)
            #pragma unroll
            for (int nt = 0; nt < 8; nt++)
                #pragma unroll
                for (int j = 0; j < 4; j++) acc[mt][nt][j] = 0.f;

        for (int ko = 0; ko < 8; ko++) {
            uint32_t kb = ko * 32;                         // 16 bf16 = 32B
            uint32_t ah[2][4], al[2][4];
            #pragma unroll
            for (int mt = 0; mt < 2; mt++) {
                ldmx4(a_hi + mt * (16 * XSTR) + kb, ah[mt]);
                ldmx4(a_lo + mt * (16 * XSTR) + kb, al[mt]);
            }
            uint32_t bh[8][2], bl[8][2];
            #pragma unroll
            for (int np = 0; np < 4; np++) {
                uint32_t tm[4];
                ldmx4(b_hi + np * (16 * XSTR) + kb, tm);
                bh[2*np][0] = tm[0]; bh[2*np][1] = tm[1];
                bh[2*np+1][0] = tm[2]; bh[2*np+1][1] = tm[3];
                ldmx4(b_lo + np * (16 * XSTR) + kb, tm);
                bl[2*np][0] = tm[0]; bl[2*np][1] = tm[1];
                bl[2*np+1][0] = tm[2]; bl[2*np+1][1] = tm[3];
            }
            #pragma unroll
            for (int mt = 0; mt < 2; mt++)
                #pragma unroll
                for (int nt = 0; nt < 8; nt++) {
                    mma16816(acc[mt][nt], ah[mt], bh[nt]);
                    mma16816(acc[mt][nt], ah[mt], bl[nt]);
                    mma16816(acc[mt][nt], al[mt], bh[nt]);
                }
        }

        // ---- epilogue: write h only ----
        int rbase = t * TILE_M + warp_m * 32 + (lane >> 2);
        int cbase = warp_n * 64 + 2 * (lane & 3);
        #pragma unroll
        for (int mt = 0; mt < 2; mt++) {
            #pragma unroll
            for (int nt = 0; nt < 8; nt++) {
                int r0 = rbase + mt * 16;
                int c = cbase + nt * 8;
                if (r0 < nrows)
                    *(float2*)&g_h[(size_t)r0 * D + c] = make_float2(acc[mt][nt][0], acc[mt][nt][1]);
                if (r0 + 8 < nrows)
                    *(float2*)&g_h[(size_t)(r0 + 8) * D + c] = make_float2(acc[mt][nt][2], acc[mt][nt][3]);
            }
        }
    }
}

// ---------------- CSR build ----------------
__global__ void k4a_hist(const int* __restrict__ ei, int E) {
    int e = blockIdx.x * 256 + threadIdx.x;
    if (e < E) atomicAdd(&g_deg[ei[e]], 1);
}
__global__ void k4b_bsum() {
    __shared__ int s[256];
    int i = blockIdx.x * 256 + threadIdx.x;
    s[threadIdx.x] = (i < MAXN) ? g_deg[i] : 0;
    __syncthreads();
    for (int o = 128; o > 0; o >>= 1) {
        if (threadIdx.x < o) s[threadIdx.x] += s[threadIdx.x + o];
        __syncthreads();
    }
    if (threadIdx.x == 0) g_bsum[blockIdx.x] = s[0];
}
__global__ void k4c_scan(int N, int E) {
    int tot = 0;
    for (int b = 0; b < NSCAN; b++) { g_bbase[b] = tot; tot += g_bsum[b]; }
    g_off[N] = E;
}
__global__ void k4d_off() {
    __shared__ int s[256];
    int i = blockIdx.x * 256 + threadIdx.x;
    int v = (i < MAXN) ? g_deg[i] : 0;
    s[threadIdx.x] = v;
    __syncthreads();
    // Hillis-Steele inclusive scan
    for (int o = 1; o < 256; o <<= 1) {
        int t = (threadIdx.x >= o) ? s[threadIdx.x - o] : 0;
        __syncthreads();
        s[threadIdx.x] += t;
        __syncthreads();
    }
    if (i < MAXN) {
        int off = g_bbase[blockIdx.x] + s[threadIdx.x] - v;
        g_off[i] = off;
        g_cur[i] = off;
    }
}
__global__ void k4e_fill(const int* __restrict__ ei, const float* __restrict__ ew, int E) {
    int e = blockIdx.x * 256 + threadIdx.x;
    if (e < E) {
        int r = ei[e];
        int p = atomicAdd(&g_cur[r], 1);
        g_ecol[p] = ei[E + e];
        g_ewt[p] = ew[e];
    }
}

// ---------------- k5: per-node gather aggregate + h*h ----------------
__global__ void __launch_bounds__(256) k5_agg(float* __restrict__ out, int N) {
    int n = blockIdx.x * 8 + (threadIdx.x >> 5);
    if (n >= N) return;
    int lane = threadIdx.x & 31;
    int s = g_off[n], e = g_off[n + 1];
    const float4* h4 = (const float4*)g_h;
    float4 acc = {0.f, 0.f, 0.f, 0.f};
    int j = s;
    for (; j + 2 <= e; j += 2) {
        int c0 = __ldg(&g_ecol[j]), c1 = __ldg(&g_ecol[j + 1]);
        float w0 = __ldg(&g_ewt[j]), w1 = __ldg(&g_ewt[j + 1]);
        float4 v0 = h4[(size_t)c0 * 32 + lane];
        float4 v1 = h4[(size_t)c1 * 32 + lane];
        acc.x = fmaf(w0, v0.x, acc.x); acc.y = fmaf(w0, v0.y, acc.y);
        acc.z = fmaf(w0, v0.z, acc.z); acc.w = fmaf(w0, v0.w, acc.w);
        acc.x = fmaf(w1, v1.x, acc.x); acc.y = fmaf(w1, v1.y, acc.y);
        acc.z = fmaf(w1, v1.z, acc.z); acc.w = fmaf(w1, v1.w, acc.w);
    }
    if (j < e) {
        int c0 = __ldg(&g_ecol[j]);
        float w0 = __ldg(&g_ewt[j]);
        float4 v0 = h4[(size_t)c0 * 32 + lane];
        acc.x = fmaf(w0, v0.x, acc.x); acc.y = fmaf(w0, v0.y, acc.y);
        acc.z = fmaf(w0, v0.z, acc.z); acc.w = fmaf(w0, v0.w, acc.w);
    }
    float4 hv = h4[(size_t)n * 32 + lane];
    float4 o;
    o.x = fmaf(hv.x, hv.x, acc.x);
    o.y = fmaf(hv.y, hv.y, acc.y);
    o.z = fmaf(hv.z, hv.z, acc.z);
    o.w = fmaf(hv.w, hv.w, acc.w);
    ((float4*)out)[(size_t)n * 32 + lane] = o;
}

// ---------------- launch ----------------
extern "C" void kernel_launch(void* const* d_in, const int* in_sizes, int n_in,
                              void* d_out, int out_size) {
    const float* n_feat = (const float*)d_in[0];
    const int*   ei     = (const int*)d_in[1];
    const float* ew     = (const float*)d_in[2];
    const float* gamma  = (const float*)d_in[3];
    const float* beta   = (const float*)d_in[4];
    const float* W      = (const float*)d_in[5];
    float* out = (float*)d_out;

    int N = in_sizes[0] / D;
    int E = in_sizes[2];
    int ntiles = (N + TILE_M - 1) / TILE_M;

    k0_prep<<<NSCAN, 256>>>(W);
    k4a_hist<<<(E + 255) / 256, 256>>>(ei, E);
    k4b_bsum<<<NSCAN, 256>>>();
    k4c_scan<<<1, 1>>>(N, E);
    k4d_off<<<NSCAN, 256>>>();
    k4e_fill<<<(E + 255) / 256, 256>>>(ei, ew, E);

    k1_stats<<<264, 256>>>((const float4*)n_feat, N);
    k2_final<<<1, D>>>(gamma, beta, 1.0f / (float)N);

    cudaFuncSetAttribute(k3_mma, cudaFuncAttributeMaxDynamicSharedMemorySize, SM_TOTAL);
    k3_mma<<<148, 256, SM_TOTAL>>>(n_feat, N, ntiles);

    k5_agg<<<(N + 7) / 8, 256>>>(out, N);
}

// round 4
// speedup vs baseline: 1.3075x; 1.1434x over previous
#include <cuda_runtime.h>
#include <cuda_bf16.h>
#include <cstdint>

#define D 128
#define MAXN 100000
#define MAXE 400000
#define TILE_M 128
#define NB256 391            // (MAXN+255)/256

// ---------------- scratch (allocation-free: device globals) ----------------
__device__ float g_stats[2 * D];                    // col sums / sumsq
__device__ float g_ab[2 * D];                       // BN affine a / b
__device__ unsigned short g_Whi[D * 136];           // bf16 hi, padded [n][k] stride 136
__device__ unsigned short g_Wlo[D * 136];           // bf16 lo
__device__ float g_h[(size_t)MAXN * D];             // h (51.2 MB)
__device__ int   g_deg[MAXN];
__device__ int   g_off[MAXN];
__device__ int   g_cur[MAXN];
__device__ int   g_total;
__device__ int   g_ecol[MAXE];
__device__ float g_ewt[MAXE];

// ---------------- helpers ----------------
__device__ __forceinline__ uint32_t smem_u32(const void* p) {
    uint32_t a;
    asm("{ .reg .u64 t; cvta.to.shared.u64 t, %1; cvt.u32.u64 %0, t; }" : "=r"(a) : "l"(p));
    return a;
}
__device__ __forceinline__ void ldmx4(uint32_t addr, uint32_t r[4]) {
    asm volatile("ldmatrix.sync.aligned.m8n8.x4.shared.b16 {%0,%1,%2,%3}, [%4];"
                 : "=r"(r[0]), "=r"(r[1]), "=r"(r[2]), "=r"(r[3]) : "r"(addr));
}
__device__ __forceinline__ void mma16816(float c[4], const uint32_t a[4], const uint32_t b[2]) {
    asm volatile("mma.sync.aligned.m16n8k16.row.col.f32.bf16.bf16.f32 "
                 "{%0,%1,%2,%3}, {%4,%5,%6,%7}, {%8,%9}, {%0,%1,%2,%3};"
                 : "+f"(c[0]), "+f"(c[1]), "+f"(c[2]), "+f"(c[3])
                 : "r"(a[0]), "r"(a[1]), "r"(a[2]), "r"(a[3]), "r"(b[0]), "r"(b[1]));
}
__device__ __forceinline__ uint32_t pkbf2(float x, float y) {
    __nv_bfloat162 t = __floats2bfloat162_rn(x, y);
    return *(uint32_t*)&t;
}

// ---------------- k0: zero stats+deg+total, build padded W bf16 hi/lo ----------------
__global__ void k0_prep(const float* __restrict__ W) {
    int i = blockIdx.x * 256 + threadIdx.x;
    if (i == 0) g_total = 0;
    if (i < 2 * D) g_stats[i] = 0.0f;
    if (i < MAXN) g_deg[i] = 0;
    if (i < D * D) {
        int n = i >> 7, k = i & 127;
        float w = W[i];
        __nv_bfloat16 hi = __float2bfloat16(w);
        float lf = w - __bfloat162float(hi);
        g_Whi[n * 136 + k] = __bfloat16_as_ushort(hi);
        g_Wlo[n * 136 + k] = __bfloat16_as_ushort(__float2bfloat16(lf));
    }
}

// ---------------- k1: column sums / sumsq ----------------
__global__ void __launch_bounds__(256) k1_stats(const float4* __restrict__ x4, int nrows) {
    int tx = threadIdx.x & 31, ty = threadIdx.x >> 5;
    float4 s = {0.f, 0.f, 0.f, 0.f}, q = {0.f, 0.f, 0.f, 0.f};
    for (int r = blockIdx.x * 8 + ty; r < nrows; r += gridDim.x * 8) {
        float4 v = x4[(size_t)r * 32 + tx];
        s.x += v.x; s.y += v.y; s.z += v.z; s.w += v.w;
        q.x += v.x * v.x; q.y += v.y * v.y; q.z += v.z * v.z; q.w += v.w * v.w;
    }
    __shared__ float4 rs[8][32], rq[8][32];
    rs[ty][tx] = s; rq[ty][tx] = q;
    __syncthreads();
    if (ty == 0) {
        for (int w = 1; w < 8; w++) {
            float4 a = rs[w][tx], b = rq[w][tx];
            s.x += a.x; s.y += a.y; s.z += a.z; s.w += a.w;
            q.x += b.x; q.y += b.y; q.z += b.z; q.w += b.w;
        }
        atomicAdd(&g_stats[4 * tx + 0], s.x);
        atomicAdd(&g_stats[4 * tx + 1], s.y);
        atomicAdd(&g_stats[4 * tx + 2], s.z);
        atomicAdd(&g_stats[4 * tx + 3], s.w);
        atomicAdd(&g_stats[D + 4 * tx + 0], q.x);
        atomicAdd(&g_stats[D + 4 * tx + 1], q.y);
        atomicAdd(&g_stats[D + 4 * tx + 2], q.z);
        atomicAdd(&g_stats[D + 4 * tx + 3], q.w);
    }
}

// ---------------- k2: finalize BN affine ----------------
__global__ void k2_final(const float* __restrict__ gamma, const float* __restrict__ beta, float inv_n) {
    int c = threadIdx.x;
    float mu  = g_stats[c] * inv_n;
    float var = fmaxf(g_stats[D + c] * inv_n - mu * mu, 0.0f);
    float a = gamma[c] * rsqrtf(var + 1e-5f);
    g_ab[c] = a;
    g_ab[D + c] = beta[c] - mu * a;
}

// ---------------- k3: HMMA bf16 2-split GEMM ----------------
#define SM_WHI 0
#define SM_WLO 34816
#define SM_XHI 69632
#define SM_XLO 104448
#define SM_TOTAL 139264
#define XSTR 272     // row stride bytes

__global__ void __launch_bounds__(256, 1) k3_mma(const float* __restrict__ x,
                                                 int nrows, int ntiles) {
    extern __shared__ __align__(16) char sm[];
    uint32_t smb = smem_u32(sm);
    int tid = threadIdx.x, wid = tid >> 5, lane = tid & 31;
    int warp_m = wid & 3;       // 4 m-blocks of 32 rows
    int warp_n = wid >> 2;      // 2 n-blocks of 64 cols

    // copy W hi/lo (padded layout) into smem
    {
        const uint4* hs = (const uint4*)g_Whi;
        const uint4* ls = (const uint4*)g_Wlo;
        uint4* hd = (uint4*)(sm + SM_WHI);
        uint4* ld = (uint4*)(sm + SM_WLO);
        for (int i = tid; i < 2176; i += 256) { hd[i] = hs[i]; ld[i] = ls[i]; }
    }

    // lane-pattern offsets for ldmatrix
    int laneRowA = (lane & 7) + ((lane >> 3) & 1) * 8;
    int laneKA   = (lane >> 4) * 8;
    int laneRowB = (lane & 7) + ((lane >> 4) & 1) * 8;
    int laneKB   = ((lane >> 3) & 1) * 8;
    uint32_t aoff = (uint32_t)((warp_m * 32 + laneRowA) * XSTR + laneKA * 2);
    uint32_t boff = (uint32_t)((warp_n * 64 + laneRowB) * XSTR + laneKB * 2);
    uint32_t a_hi = smb + SM_XHI + aoff, a_lo = smb + SM_XLO + aoff;
    uint32_t b_hi = smb + SM_WHI + boff, b_lo = smb + SM_WLO + boff;

    const float4* x4 = (const float4*)x;
    const float4* ab4 = (const float4*)g_ab;

    for (int t = blockIdx.x; t < ntiles; t += gridDim.x) {
        // ---- stage X tile: normalize -> relu -> bf16 hi/lo ----
        __syncthreads();
        #pragma unroll
        for (int it = 0; it < 16; it++) {
            int ci = tid + it * 256;          // 0..4095 over [128 rows][32 quads]
            int r = ci >> 5, cq = ci & 31;
            int gr = t * TILE_M + r;
            float4 v = {0.f, 0.f, 0.f, 0.f};
            if (gr < nrows) v = x4[(size_t)gr * 32 + cq];
            float4 a = __ldg(&ab4[cq]), b = __ldg(&ab4[32 + cq]);
            float y0 = fmaxf(fmaf(a.x, v.x, b.x), 0.f);
            float y1 = fmaxf(fmaf(a.y, v.y, b.y), 0.f);
            float y2 = fmaxf(fmaf(a.z, v.z, b.z), 0.f);
            float y3 = fmaxf(fmaf(a.w, v.w, b.w), 0.f);
            __nv_bfloat16 h0 = __float2bfloat16(y0), h1 = __float2bfloat16(y1);
            __nv_bfloat16 h2 = __float2bfloat16(y2), h3 = __float2bfloat16(y3);
            uint2 hiw, low;
            hiw.x = (uint32_t)__bfloat16_as_ushort(h0) | ((uint32_t)__bfloat16_as_ushort(h1) << 16);
            hiw.y = (uint32_t)__bfloat16_as_ushort(h2) | ((uint32_t)__bfloat16_as_ushort(h3) << 16);
            low.x = pkbf2(y0 - __bfloat162float(h0), y1 - __bfloat162float(h1));
            low.y = pkbf2(y2 - __bfloat162float(h2), y3 - __bfloat162float(h3));
            uint32_t off = (uint32_t)(r * XSTR + cq * 8);
            *(uint2*)(sm + SM_XHI + off) = hiw;
            *(uint2*)(sm + SM_XLO + off) = low;
        }
        __syncthreads();

        // ---- mainloop: 8 k16-steps x 3 products ----
        float acc[2][8][4];
        #pragma unroll
        for (int mt = 0; mt < 2; mt++)
            #pragma unroll
            for (int nt = 0; nt < 8; nt++)
                #pragma unroll
                for (int j = 0; j < 4; j++) acc[mt][nt][j] = 0.f;

        for (int ko = 0; ko < 8; ko++) {
            uint32_t kb = ko * 32;
            uint32_t ah[2][4], al[2][4];
            #pragma unroll
            for (int mt = 0; mt < 2; mt++) {
                ldmx4(a_hi + mt * (16 * XSTR) + kb, ah[mt]);
                ldmx4(a_lo + mt * (16 * XSTR) + kb, al[mt]);
            }
            uint32_t bh[8][2], bl[8][2];
            #pragma unroll
            for (int np = 0; np < 4; np++) {
                uint32_t tm[4];
                ldmx4(b_hi + np * (16 * XSTR) + kb, tm);
                bh[2*np][0] = tm[0]; bh[2*np][1] = tm[1];
                bh[2*np+1][0] = tm[2]; bh[2*np+1][1] = tm[3];
                ldmx4(b_lo + np * (16 * XSTR) + kb, tm);
                bl[2*np][0] = tm[0]; bl[2*np][1] = tm[1];
                bl[2*np+1][0] = tm[2]; bl[2*np+1][1] = tm[3];
            }
            #pragma unroll
            for (int mt = 0; mt < 2; mt++)
                #pragma unroll
                for (int nt = 0; nt < 8; nt++) {
                    mma16816(acc[mt][nt], ah[mt], bh[nt]);
                    mma16816(acc[mt][nt], ah[mt], bl[nt]);
                    mma16816(acc[mt][nt], al[mt], bh[nt]);
                }
        }

        // ---- epilogue: write h ----
        int rbase = t * TILE_M + warp_m * 32 + (lane >> 2);
        int cbase = warp_n * 64 + 2 * (lane & 3);
        #pragma unroll
        for (int mt = 0; mt < 2; mt++) {
            #pragma unroll
            for (int nt = 0; nt < 8; nt++) {
                int r0 = rbase + mt * 16;
                int c = cbase + nt * 8;
                if (r0 < nrows)
                    *(float2*)&g_h[(size_t)r0 * D + c] = make_float2(acc[mt][nt][0], acc[mt][nt][1]);
                if (r0 + 8 < nrows)
                    *(float2*)&g_h[(size_t)(r0 + 8) * D + c] = make_float2(acc[mt][nt][2], acc[mt][nt][3]);
            }
        }
    }
}

// ---------------- CSR build ----------------
__global__ void k4a_hist(const int* __restrict__ ei, int E) {
    int e = blockIdx.x * 256 + threadIdx.x;
    if (e < E) atomicAdd(&g_deg[ei[e]], 1);
}
// warp-aggregated segment allocator: offsets need not be globally ordered,
// only disjoint — k5 consumes [off, off+deg).
__global__ void __launch_bounds__(256) k4b_off(int N) {
    int i = blockIdx.x * 256 + threadIdx.x;
    int lane = threadIdx.x & 31;
    int v = (i < N) ? g_deg[i] : 0;
    int incl = v;
    #pragma unroll
    for (int o = 1; o < 32; o <<= 1) {
        int t = __shfl_up_sync(0xFFFFFFFFu, incl, o);
        if (lane >= o) incl += t;
    }
    int wsum = __shfl_sync(0xFFFFFFFFu, incl, 31);
    int base = 0;
    if (lane == 0) base = atomicAdd(&g_total, wsum);
    base = __shfl_sync(0xFFFFFFFFu, base, 0);
    if (i < N) {
        int off = base + incl - v;
        g_off[i] = off;
        g_cur[i] = off;
    }
}
__global__ void k4c_fill(const int* __restrict__ ei, const float* __restrict__ ew, int E) {
    int e = blockIdx.x * 256 + threadIdx.x;
    if (e < E) {
        int r = ei[e];
        int p = atomicAdd(&g_cur[r], 1);
        g_ecol[p] = ei[E + e];
        g_ewt[p] = ew[e];
    }
}

// ---------------- k5: per-node gather aggregate + h*h ----------------
__global__ void __launch_bounds__(256) k5_agg(float* __restrict__ out, int N) {
    int n = blockIdx.x * 8 + (threadIdx.x >> 5);
    if (n >= N) return;
    int lane = threadIdx.x & 31;
    int s = g_off[n];
    int e = s + g_deg[n];
    const float4* h4 = (const float4*)g_h;
    float4 acc = {0.f, 0.f, 0.f, 0.f};
    int j = s;
    for (; j + 2 <= e; j += 2) {
        int c0 = __ldg(&g_ecol[j]), c1 = __ldg(&g_ecol[j + 1]);
        float w0 = __ldg(&g_ewt[j]), w1 = __ldg(&g_ewt[j + 1]);
        float4 v0 = h4[(size_t)c0 * 32 + lane];
        float4 v1 = h4[(size_t)c1 * 32 + lane];
        acc.x = fmaf(w0, v0.x, acc.x); acc.y = fmaf(w0, v0.y, acc.y);
        acc.z = fmaf(w0, v0.z, acc.z); acc.w = fmaf(w0, v0.w, acc.w);
        acc.x = fmaf(w1, v1.x, acc.x); acc.y = fmaf(w1, v1.y, acc.y);
        acc.z = fmaf(w1, v1.z, acc.z); acc.w = fmaf(w1, v1.w, acc.w);
    }
    if (j < e) {
        int c0 = __ldg(&g_ecol[j]);
        float w0 = __ldg(&g_ewt[j]);
        float4 v0 = h4[(size_t)c0 * 32 + lane];
        acc.x = fmaf(w0, v0.x, acc.x); acc.y = fmaf(w0, v0.y, acc.y);
        acc.z = fmaf(w0, v0.z, acc.z); acc.w = fmaf(w0, v0.w, acc.w);
    }
    float4 hv = h4[(size_t)n * 32 + lane];
    float4 o;
    o.x = fmaf(hv.x, hv.x, acc.x);
    o.y = fmaf(hv.y, hv.y, acc.y);
    o.z = fmaf(hv.z, hv.z, acc.z);
    o.w = fmaf(hv.w, hv.w, acc.w);
    ((float4*)out)[(size_t)n * 32 + lane] = o;
}

// ---------------- launch ----------------
extern "C" void kernel_launch(void* const* d_in, const int* in_sizes, int n_in,
                              void* d_out, int out_size) {
    const float* n_feat = (const float*)d_in[0];
    const int*   ei     = (const int*)d_in[1];
    const float* ew     = (const float*)d_in[2];
    const float* gamma  = (const float*)d_in[3];
    const float* beta   = (const float*)d_in[4];
    const float* W      = (const float*)d_in[5];
    float* out = (float*)d_out;

    int N = in_sizes[0] / D;
    int E = in_sizes[2];
    int ntiles = (N + TILE_M - 1) / TILE_M;

    k0_prep<<<NB256, 256>>>(W);
    k4a_hist<<<(E + 255) / 256, 256>>>(ei, E);
    k4b_off<<<(N + 255) / 256, 256>>>(N);
    k4c_fill<<<(E + 255) / 256, 256>>>(ei, ew, E);

    k1_stats<<<264, 256>>>((const float4*)n_feat, N);
    k2_final<<<1, D>>>(gamma, beta, 1.0f / (float)N);

    cudaFuncSetAttribute(k3_mma, cudaFuncAttributeMaxDynamicSharedMemorySize, SM_TOTAL);
    k3_mma<<<148, 256, SM_TOTAL>>>(n_feat, N, ntiles);

    k5_agg<<<(N + 7) / 8, 256>>>(out, N);
}

// round 5
// speedup vs baseline: 1.3636x; 1.0428x over previous
#include <cuda_runtime.h>
#include <cuda_bf16.h>
#include <cstdint>

#define D 128
#define MAXN 100000
#define MAXE 400000
#define TILE_M 64
#define NB256 391            // (MAXN+255)/256

// ---------------- scratch (allocation-free: device globals) ----------------
__device__ float g_stats[2 * D];                    // col sums / sumsq
__device__ float g_ab[2 * D];                       // BN affine a / b
__device__ unsigned short g_Whi[D * 136];           // bf16 hi, padded [n][k] stride 136
__device__ unsigned short g_Wlo[D * 136];           // bf16 lo
__device__ float g_h[(size_t)MAXN * D];             // h (51.2 MB)
__device__ int   g_deg[MAXN];
__device__ int   g_off[MAXN];
__device__ int   g_cur[MAXN];
__device__ int   g_total;
__device__ int   g_ecol[MAXE];
__device__ float g_ewt[MAXE];

// ---------------- helpers ----------------
__device__ __forceinline__ uint32_t smem_u32(const void* p) {
    uint32_t a;
    asm("{ .reg .u64 t; cvta.to.shared.u64 t, %1; cvt.u32.u64 %0, t; }" : "=r"(a) : "l"(p));
    return a;
}
__device__ __forceinline__ void ldmx4(uint32_t addr, uint32_t r[4]) {
    asm volatile("ldmatrix.sync.aligned.m8n8.x4.shared.b16 {%0,%1,%2,%3}, [%4];"
                 : "=r"(r[0]), "=r"(r[1]), "=r"(r[2]), "=r"(r[3]) : "r"(addr));
}
__device__ __forceinline__ void mma16816(float c[4], const uint32_t a[4], const uint32_t b[2]) {
    asm volatile("mma.sync.aligned.m16n8k16.row.col.f32.bf16.bf16.f32 "
                 "{%0,%1,%2,%3}, {%4,%5,%6,%7}, {%8,%9}, {%0,%1,%2,%3};"
                 : "+f"(c[0]), "+f"(c[1]), "+f"(c[2]), "+f"(c[3])
                 : "r"(a[0]), "r"(a[1]), "r"(a[2]), "r"(a[3]), "r"(b[0]), "r"(b[1]));
}
__device__ __forceinline__ uint32_t pkbf2(float x, float y) {
    __nv_bfloat162 t = __floats2bfloat162_rn(x, y);
    return *(uint32_t*)&t;
}

// ---------------- k0: zero stats+deg+total, build padded W bf16 hi/lo ----------------
__global__ void k0_prep(const float* __restrict__ W) {
    int i = blockIdx.x * 256 + threadIdx.x;
    if (i == 0) g_total = 0;
    if (i < 2 * D) g_stats[i] = 0.0f;
    if (i < MAXN) g_deg[i] = 0;
    if (i < D * D) {
        int n = i >> 7, k = i & 127;
        float w = W[i];
        __nv_bfloat16 hi = __float2bfloat16(w);
        float lf = w - __bfloat162float(hi);
        g_Whi[n * 136 + k] = __bfloat16_as_ushort(hi);
        g_Wlo[n * 136 + k] = __bfloat16_as_ushort(__float2bfloat16(lf));
    }
}

// ---------------- k1: column sums / sumsq ----------------
__global__ void __launch_bounds__(256) k1_stats(const float4* __restrict__ x4, int nrows) {
    int tx = threadIdx.x & 31, ty = threadIdx.x >> 5;
    float4 s = {0.f, 0.f, 0.f, 0.f}, q = {0.f, 0.f, 0.f, 0.f};
    for (int r = blockIdx.x * 8 + ty; r < nrows; r += gridDim.x * 8) {
        float4 v = x4[(size_t)r * 32 + tx];
        s.x += v.x; s.y += v.y; s.z += v.z; s.w += v.w;
        q.x += v.x * v.x; q.y += v.y * v.y; q.z += v.z * v.z; q.w += v.w * v.w;
    }
    __shared__ float4 rs[8][32], rq[8][32];
    rs[ty][tx] = s; rq[ty][tx] = q;
    __syncthreads();
    if (ty == 0) {
        for (int w = 1; w < 8; w++) {
            float4 a = rs[w][tx], b = rq[w][tx];
            s.x += a.x; s.y += a.y; s.z += a.z; s.w += a.w;
            q.x += b.x; q.y += b.y; q.z += b.z; q.w += b.w;
        }
        atomicAdd(&g_stats[4 * tx + 0], s.x);
        atomicAdd(&g_stats[4 * tx + 1], s.y);
        atomicAdd(&g_stats[4 * tx + 2], s.z);
        atomicAdd(&g_stats[4 * tx + 3], s.w);
        atomicAdd(&g_stats[D + 4 * tx + 0], q.x);
        atomicAdd(&g_stats[D + 4 * tx + 1], q.y);
        atomicAdd(&g_stats[D + 4 * tx + 2], q.z);
        atomicAdd(&g_stats[D + 4 * tx + 3], q.w);
    }
}

// ---------------- k2: finalize BN affine ----------------
__global__ void k2_final(const float* __restrict__ gamma, const float* __restrict__ beta, float inv_n) {
    int c = threadIdx.x;
    float mu  = g_stats[c] * inv_n;
    float var = fmaxf(g_stats[D + c] * inv_n - mu * mu, 0.0f);
    float a = gamma[c] * rsqrtf(var + 1e-5f);
    g_ab[c] = a;
    g_ab[D + c] = beta[c] - mu * a;
}

// ---------------- k3: HMMA bf16 2-split GEMM, TILE_M=64, 2 CTAs/SM ----------------
// smem: Whi(34816) | Wlo(34816) | Xhi(17408) | Xlo(17408) = 104448 B per CTA
#define SM_WHI 0
#define SM_WLO 34816
#define SM_XHI 69632
#define SM_XLO 87040
#define SM_TOTAL 104448
#define XSTR 272     // row stride bytes

__global__ void __launch_bounds__(256, 2) k3_mma(const float* __restrict__ x,
                                                 int nrows, int ntiles) {
    extern __shared__ __align__(16) char sm[];
    uint32_t smb = smem_u32(sm);
    int tid = threadIdx.x, wid = tid >> 5, lane = tid & 31;
    int warp_m = wid & 1;       // 2 m-blocks of 32 rows
    int warp_n = wid >> 1;      // 4 n-blocks of 32 cols

    // copy W hi/lo (padded layout) into smem
    {
        const uint4* hs = (const uint4*)g_Whi;
        const uint4* ls = (const uint4*)g_Wlo;
        uint4* hd = (uint4*)(sm + SM_WHI);
        uint4* ld = (uint4*)(sm + SM_WLO);
        for (int i = tid; i < 2176; i += 256) { hd[i] = hs[i]; ld[i] = ls[i]; }
    }

    // lane-pattern offsets for ldmatrix
    int laneRowA = (lane & 7) + ((lane >> 3) & 1) * 8;
    int laneKA   = (lane >> 4) * 8;
    int laneRowB = (lane & 7) + ((lane >> 4) & 1) * 8;
    int laneKB   = ((lane >> 3) & 1) * 8;
    uint32_t aoff = (uint32_t)((warp_m * 32 + laneRowA) * XSTR + laneKA * 2);
    uint32_t boff = (uint32_t)((warp_n * 32 + laneRowB) * XSTR + laneKB * 2);
    uint32_t a_hi = smb + SM_XHI + aoff, a_lo = smb + SM_XLO + aoff;
    uint32_t b_hi = smb + SM_WHI + boff, b_lo = smb + SM_WLO + boff;

    const float4* x4 = (const float4*)x;
    const float4* ab4 = (const float4*)g_ab;

    for (int t = blockIdx.x; t < ntiles; t += gridDim.x) {
        // ---- stage X tile: normalize -> relu -> bf16 hi/lo ----
        __syncthreads();
        #pragma unroll
        for (int it = 0; it < 8; it++) {
            int ci = tid + it * 256;          // 0..2047 over [64 rows][32 quads]
            int r = ci >> 5, cq = ci & 31;
            int gr = t * TILE_M + r;
            float4 v = {0.f, 0.f, 0.f, 0.f};
            if (gr < nrows) v = x4[(size_t)gr * 32 + cq];
            float4 a = __ldg(&ab4[cq]), b = __ldg(&ab4[32 + cq]);
            float y0 = fmaxf(fmaf(a.x, v.x, b.x), 0.f);
            float y1 = fmaxf(fmaf(a.y, v.y, b.y), 0.f);
            float y2 = fmaxf(fmaf(a.z, v.z, b.z), 0.f);
            float y3 = fmaxf(fmaf(a.w, v.w, b.w), 0.f);
            __nv_bfloat16 h0 = __float2bfloat16(y0), h1 = __float2bfloat16(y1);
            __nv_bfloat16 h2 = __float2bfloat16(y2), h3 = __float2bfloat16(y3);
            uint2 hiw, low;
            hiw.x = (uint32_t)__bfloat16_as_ushort(h0) | ((uint32_t)__bfloat16_as_ushort(h1) << 16);
            hiw.y = (uint32_t)__bfloat16_as_ushort(h2) | ((uint32_t)__bfloat16_as_ushort(h3) << 16);
            low.x = pkbf2(y0 - __bfloat162float(h0), y1 - __bfloat162float(h1));
            low.y = pkbf2(y2 - __bfloat162float(h2), y3 - __bfloat162float(h3));
            uint32_t off = (uint32_t)(r * XSTR + cq * 8);
            *(uint2*)(sm + SM_XHI + off) = hiw;
            *(uint2*)(sm + SM_XLO + off) = low;
        }
        __syncthreads();

        // ---- mainloop: 8 k16-steps x 3 products ----
        float acc[2][4][4];
        #pragma unroll
        for (int mt = 0; mt < 2; mt++)
            #pragma unroll
            for (int nt = 0; nt < 4; nt++)
                #pragma unroll
                for (int j = 0; j < 4; j++) acc[mt][nt][j] = 0.f;

        for (int ko = 0; ko < 8; ko++) {
            uint32_t kb = ko * 32;
            uint32_t ah[2][4], al[2][4];
            #pragma unroll
            for (int mt = 0; mt < 2; mt++) {
                ldmx4(a_hi + mt * (16 * XSTR) + kb, ah[mt]);
                ldmx4(a_lo + mt * (16 * XSTR) + kb, al[mt]);
            }
            uint32_t bh[4][2], bl[4][2];
            #pragma unroll
            for (int np = 0; np < 2; np++) {
                uint32_t tm[4];
                ldmx4(b_hi + np * (16 * XSTR) + kb, tm);
                bh[2*np][0] = tm[0]; bh[2*np][1] = tm[1];
                bh[2*np+1][0] = tm[2]; bh[2*np+1][1] = tm[3];
                ldmx4(b_lo + np * (16 * XSTR) + kb, tm);
                bl[2*np][0] = tm[0]; bl[2*np][1] = tm[1];
                bl[2*np+1][0] = tm[2]; bl[2*np+1][1] = tm[3];
            }
            #pragma unroll
            for (int mt = 0; mt < 2; mt++)
                #pragma unroll
                for (int nt = 0; nt < 4; nt++) {
                    mma16816(acc[mt][nt], ah[mt], bh[nt]);
                    mma16816(acc[mt][nt], ah[mt], bl[nt]);
                    mma16816(acc[mt][nt], al[mt], bh[nt]);
                }
        }

        // ---- epilogue: write h ----
        int rbase = t * TILE_M + warp_m * 32 + (lane >> 2);
        int cbase = warp_n * 32 + 2 * (lane & 3);
        #pragma unroll
        for (int mt = 0; mt < 2; mt++) {
            #pragma unroll
            for (int nt = 0; nt < 4; nt++) {
                int r0 = rbase + mt * 16;
                int c = cbase + nt * 8;
                if (r0 < nrows)
                    *(float2*)&g_h[(size_t)r0 * D + c] = make_float2(acc[mt][nt][0], acc[mt][nt][1]);
                if (r0 + 8 < nrows)
                    *(float2*)&g_h[(size_t)(r0 + 8) * D + c] = make_float2(acc[mt][nt][2], acc[mt][nt][3]);
            }
        }
    }
}

// ---------------- CSR build ----------------
__global__ void k4a_hist(const int* __restrict__ ei, int E) {
    int e = blockIdx.x * 256 + threadIdx.x;
    if (e < E) atomicAdd(&g_deg[ei[e]], 1);
}
__global__ void __launch_bounds__(256) k4b_off(int N) {
    int i = blockIdx.x * 256 + threadIdx.x;
    int lane = threadIdx.x & 31;
    int v = (i < N) ? g_deg[i] : 0;
    int incl = v;
    #pragma unroll
    for (int o = 1; o < 32; o <<= 1) {
        int t = __shfl_up_sync(0xFFFFFFFFu, incl, o);
        if (lane >= o) incl += t;
    }
    int wsum = __shfl_sync(0xFFFFFFFFu, incl, 31);
    int base = 0;
    if (lane == 0) base = atomicAdd(&g_total, wsum);
    base = __shfl_sync(0xFFFFFFFFu, base, 0);
    if (i < N) {
        int off = base + incl - v;
        g_off[i] = off;
        g_cur[i] = off;
    }
}
__global__ void k4c_fill(const int* __restrict__ ei, const float* __restrict__ ew, int E) {
    int e = blockIdx.x * 256 + threadIdx.x;
    if (e < E) {
        int r = ei[e];
        int p = atomicAdd(&g_cur[r], 1);
        g_ecol[p] = ei[E + e];
        g_ewt[p] = ew[e];
    }
}

// ---------------- k5: per-node gather aggregate + h*h ----------------
__global__ void __launch_bounds__(256) k5_agg(float* __restrict__ out, int N) {
    int n = blockIdx.x * 8 + (threadIdx.x >> 5);
    if (n >= N) return;
    int lane = threadIdx.x & 31;
    int s = g_off[n];
    int e = s + g_deg[n];
    const float4* h4 = (const float4*)g_h;
    float4 acc = {0.f, 0.f, 0.f, 0.f};
    int j = s;
    for (; j + 2 <= e; j += 2) {
        int c0 = __ldg(&g_ecol[j]), c1 = __ldg(&g_ecol[j + 1]);
        float w0 = __ldg(&g_ewt[j]), w1 = __ldg(&g_ewt[j + 1]);
        float4 v0 = h4[(size_t)c0 * 32 + lane];
        float4 v1 = h4[(size_t)c1 * 32 + lane];
        acc.x = fmaf(w0, v0.x, acc.x); acc.y = fmaf(w0, v0.y, acc.y);
        acc.z = fmaf(w0, v0.z, acc.z); acc.w = fmaf(w0, v0.w, acc.w);
        acc.x = fmaf(w1, v1.x, acc.x); acc.y = fmaf(w1, v1.y, acc.y);
        acc.z = fmaf(w1, v1.z, acc.z); acc.w = fmaf(w1, v1.w, acc.w);
    }
    if (j < e) {
        int c0 = __ldg(&g_ecol[j]);
        float w0 = __ldg(&g_ewt[j]);
        float4 v0 = h4[(size_t)c0 * 32 + lane];
        acc.x = fmaf(w0, v0.x, acc.x); acc.y = fmaf(w0, v0.y, acc.y);
        acc.z = fmaf(w0, v0.z, acc.z); acc.w = fmaf(w0, v0.w, acc.w);
    }
    float4 hv = h4[(size_t)n * 32 + lane];
    float4 o;
    o.x = fmaf(hv.x, hv.x, acc.x);
    o.y = fmaf(hv.y, hv.y, acc.y);
    o.z = fmaf(hv.z, hv.z, acc.z);
    o.w = fmaf(hv.w, hv.w, acc.w);
    // streaming store: don't evict h from L2
    __stcs(&((float4*)out)[(size_t)n * 32 + lane], o);
}

// ---------------- launch ----------------
extern "C" void kernel_launch(void* const* d_in, const int* in_sizes, int n_in,
                              void* d_out, int out_size) {
    const float* n_feat = (const float*)d_in[0];
    const int*   ei     = (const int*)d_in[1];
    const float* ew     = (const float*)d_in[2];
    const float* gamma  = (const float*)d_in[3];
    const float* beta   = (const float*)d_in[4];
    const float* W      = (const float*)d_in[5];
    float* out = (float*)d_out;

    int N = in_sizes[0] / D;
    int E = in_sizes[2];
    int ntiles = (N + TILE_M - 1) / TILE_M;

    k0_prep<<<NB256, 256>>>(W);
    k4a_hist<<<(E + 255) / 256, 256>>>(ei, E);
    k4b_off<<<(N + 255) / 256, 256>>>(N);
    k4c_fill<<<(E + 255) / 256, 256>>>(ei, ew, E);

    k1_stats<<<264, 256>>>((const float4*)n_feat, N);
    k2_final<<<1, D>>>(gamma, beta, 1.0f / (float)N);

    cudaFuncSetAttribute(k3_mma, cudaFuncAttributeMaxDynamicSharedMemorySize, SM_TOTAL);
    k3_mma<<<296, 256, SM_TOTAL>>>(n_feat, N, ntiles);

    k5_agg<<<(N + 7) / 8, 256>>>(out, N);
}

// round 6
// speedup vs baseline: 1.4873x; 1.0907x over previous
#include <cuda_runtime.h>
#include <cuda_bf16.h>
#include <cstdint>

#define D 128
#define MAXN 100000
#define MAXE 400000
#define TILE_M 64
#define NB256 391            // (MAXN+255)/256

// ---------------- scratch (allocation-free: device globals) ----------------
__device__ float g_stats[2 * D];                    // col sums / sumsq
__device__ float g_ab[2 * D];                       // BN affine a / b
__device__ unsigned short g_Whi[D * 136];           // bf16 hi, padded [n][k] stride 136
__device__ unsigned short g_Wlo[D * 136];           // bf16 lo
__device__ float g_h[(size_t)MAXN * D];             // h (51.2 MB)
__device__ int   g_deg[MAXN];
__device__ int   g_off[MAXN];
__device__ int   g_cur[MAXN];
__device__ int   g_total;
__device__ int   g_ecol[MAXE];
__device__ float g_ewt[MAXE];

// ---------------- helpers ----------------
__device__ __forceinline__ uint32_t smem_u32(const void* p) {
    uint32_t a;
    asm("{ .reg .u64 t; cvta.to.shared.u64 t, %1; cvt.u32.u64 %0, t; }" : "=r"(a) : "l"(p));
    return a;
}
__device__ __forceinline__ void ldmx4(uint32_t addr, uint32_t r[4]) {
    asm volatile("ldmatrix.sync.aligned.m8n8.x4.shared.b16 {%0,%1,%2,%3}, [%4];"
                 : "=r"(r[0]), "=r"(r[1]), "=r"(r[2]), "=r"(r[3]) : "r"(addr));
}
__device__ __forceinline__ void mma16816(float c[4], const uint32_t a[4], const uint32_t b[2]) {
    asm volatile("mma.sync.aligned.m16n8k16.row.col.f32.bf16.bf16.f32 "
                 "{%0,%1,%2,%3}, {%4,%5,%6,%7}, {%8,%9}, {%0,%1,%2,%3};"
                 : "+f"(c[0]), "+f"(c[1]), "+f"(c[2]), "+f"(c[3])
                 : "r"(a[0]), "r"(a[1]), "r"(a[2]), "r"(a[3]), "r"(b[0]), "r"(b[1]));
}
__device__ __forceinline__ uint32_t pkbf2(float x, float y) {
    __nv_bfloat162 t = __floats2bfloat162_rn(x, y);
    return *(uint32_t*)&t;
}

// ---------------- k0: zero stats+deg+total, build padded W bf16 hi/lo ----------------
__global__ void k0_prep(const float* __restrict__ W) {
    int i = blockIdx.x * 256 + threadIdx.x;
    if (i == 0) g_total = 0;
    if (i < 2 * D) g_stats[i] = 0.0f;
    if (i < MAXN) g_deg[i] = 0;
    if (i < D * D) {
        int n = i >> 7, k = i & 127;
        float w = W[i];
        __nv_bfloat16 hi = __float2bfloat16(w);
        float lf = w - __bfloat162float(hi);
        g_Whi[n * 136 + k] = __bfloat16_as_ushort(hi);
        g_Wlo[n * 136 + k] = __bfloat16_as_ushort(__float2bfloat16(lf));
    }
}

// ---------------- k1: column sums / sumsq ----------------
__global__ void __launch_bounds__(256) k1_stats(const float4* __restrict__ x4, int nrows) {
    int tx = threadIdx.x & 31, ty = threadIdx.x >> 5;
    float4 s = {0.f, 0.f, 0.f, 0.f}, q = {0.f, 0.f, 0.f, 0.f};
    for (int r = blockIdx.x * 8 + ty; r < nrows; r += gridDim.x * 8) {
        float4 v = x4[(size_t)r * 32 + tx];
        s.x += v.x; s.y += v.y; s.z += v.z; s.w += v.w;
        q.x += v.x * v.x; q.y += v.y * v.y; q.z += v.z * v.z; q.w += v.w * v.w;
    }
    __shared__ float4 rs[8][32], rq[8][32];
    rs[ty][tx] = s; rq[ty][tx] = q;
    __syncthreads();
    if (ty == 0) {
        for (int w = 1; w < 8; w++) {
            float4 a = rs[w][tx], b = rq[w][tx];
            s.x += a.x; s.y += a.y; s.z += a.z; s.w += a.w;
            q.x += b.x; q.y += b.y; q.z += b.z; q.w += b.w;
        }
        atomicAdd(&g_stats[4 * tx + 0], s.x);
        atomicAdd(&g_stats[4 * tx + 1], s.y);
        atomicAdd(&g_stats[4 * tx + 2], s.z);
        atomicAdd(&g_stats[4 * tx + 3], s.w);
        atomicAdd(&g_stats[D + 4 * tx + 0], q.x);
        atomicAdd(&g_stats[D + 4 * tx + 1], q.y);
        atomicAdd(&g_stats[D + 4 * tx + 2], q.z);
        atomicAdd(&g_stats[D + 4 * tx + 3], q.w);
    }
}

// ---------------- k2: finalize BN affine ----------------
__global__ void k2_final(const float* __restrict__ gamma, const float* __restrict__ beta, float inv_n) {
    int c = threadIdx.x;
    float mu  = g_stats[c] * inv_n;
    float var = fmaxf(g_stats[D + c] * inv_n - mu * mu, 0.0f);
    float a = gamma[c] * rsqrtf(var + 1e-5f);
    g_ab[c] = a;
    g_ab[D + c] = beta[c] - mu * a;
}

// ---------------- k3: HMMA bf16 2-split GEMM, TILE_M=64, 2 CTAs/SM ----------------
#define SM_WHI 0
#define SM_WLO 34816
#define SM_XHI 69632
#define SM_XLO 87040
#define SM_TOTAL 104448
#define XSTR 272     // row stride bytes

__global__ void __launch_bounds__(256, 2) k3_mma(const float* __restrict__ x,
                                                 int nrows, int ntiles) {
    extern __shared__ __align__(16) char sm[];
    uint32_t smb = smem_u32(sm);
    int tid = threadIdx.x, wid = tid >> 5, lane = tid & 31;
    int warp_m = wid & 1;       // 2 m-blocks of 32 rows
    int warp_n = wid >> 1;      // 4 n-blocks of 32 cols

    {
        const uint4* hs = (const uint4*)g_Whi;
        const uint4* ls = (const uint4*)g_Wlo;
        uint4* hd = (uint4*)(sm + SM_WHI);
        uint4* ld = (uint4*)(sm + SM_WLO);
        for (int i = tid; i < 2176; i += 256) { hd[i] = hs[i]; ld[i] = ls[i]; }
    }

    int laneRowA = (lane & 7) + ((lane >> 3) & 1) * 8;
    int laneKA   = (lane >> 4) * 8;
    int laneRowB = (lane & 7) + ((lane >> 4) & 1) * 8;
    int laneKB   = ((lane >> 3) & 1) * 8;
    uint32_t aoff = (uint32_t)((warp_m * 32 + laneRowA) * XSTR + laneKA * 2);
    uint32_t boff = (uint32_t)((warp_n * 32 + laneRowB) * XSTR + laneKB * 2);
    uint32_t a_hi = smb + SM_XHI + aoff, a_lo = smb + SM_XLO + aoff;
    uint32_t b_hi = smb + SM_WHI + boff, b_lo = smb + SM_WLO + boff;

    const float4* x4 = (const float4*)x;
    const float4* ab4 = (const float4*)g_ab;

    for (int t = blockIdx.x; t < ntiles; t += gridDim.x) {
        __syncthreads();
        #pragma unroll
        for (int it = 0; it < 8; it++) {
            int ci = tid + it * 256;
            int r = ci >> 5, cq = ci & 31;
            int gr = t * TILE_M + r;
            float4 v = {0.f, 0.f, 0.f, 0.f};
            if (gr < nrows) v = x4[(size_t)gr * 32 + cq];
            float4 a = __ldg(&ab4[cq]), b = __ldg(&ab4[32 + cq]);
            float y0 = fmaxf(fmaf(a.x, v.x, b.x), 0.f);
            float y1 = fmaxf(fmaf(a.y, v.y, b.y), 0.f);
            float y2 = fmaxf(fmaf(a.z, v.z, b.z), 0.f);
            float y3 = fmaxf(fmaf(a.w, v.w, b.w), 0.f);
            __nv_bfloat16 h0 = __float2bfloat16(y0), h1 = __float2bfloat16(y1);
            __nv_bfloat16 h2 = __float2bfloat16(y2), h3 = __float2bfloat16(y3);
            uint2 hiw, low;
            hiw.x = (uint32_t)__bfloat16_as_ushort(h0) | ((uint32_t)__bfloat16_as_ushort(h1) << 16);
            hiw.y = (uint32_t)__bfloat16_as_ushort(h2) | ((uint32_t)__bfloat16_as_ushort(h3) << 16);
            low.x = pkbf2(y0 - __bfloat162float(h0), y1 - __bfloat162float(h1));
            low.y = pkbf2(y2 - __bfloat162float(h2), y3 - __bfloat162float(h3));
            uint32_t off = (uint32_t)(r * XSTR + cq * 8);
            *(uint2*)(sm + SM_XHI + off) = hiw;
            *(uint2*)(sm + SM_XLO + off) = low;
        }
        __syncthreads();

        float acc[2][4][4];
        #pragma unroll
        for (int mt = 0; mt < 2; mt++)
            #pragma unroll
            for (int nt = 0; nt < 4; nt++)
                #pragma unroll
                for (int j = 0; j < 4; j++) acc[mt][nt][j] = 0.f;

        for (int ko = 0; ko < 8; ko++) {
            uint32_t kb = ko * 32;
            uint32_t ah[2][4], al[2][4];
            #pragma unroll
            for (int mt = 0; mt < 2; mt++) {
                ldmx4(a_hi + mt * (16 * XSTR) + kb, ah[mt]);
                ldmx4(a_lo + mt * (16 * XSTR) + kb, al[mt]);
            }
            uint32_t bh[4][2], bl[4][2];
            #pragma unroll
            for (int np = 0; np < 2; np++) {
                uint32_t tm[4];
                ldmx4(b_hi + np * (16 * XSTR) + kb, tm);
                bh[2*np][0] = tm[0]; bh[2*np][1] = tm[1];
                bh[2*np+1][0] = tm[2]; bh[2*np+1][1] = tm[3];
                ldmx4(b_lo + np * (16 * XSTR) + kb, tm);
                bl[2*np][0] = tm[0]; bl[2*np][1] = tm[1];
                bl[2*np+1][0] = tm[2]; bl[2*np+1][1] = tm[3];
            }
            #pragma unroll
            for (int mt = 0; mt < 2; mt++)
                #pragma unroll
                for (int nt = 0; nt < 4; nt++) {
                    mma16816(acc[mt][nt], ah[mt], bh[nt]);
                    mma16816(acc[mt][nt], ah[mt], bl[nt]);
                    mma16816(acc[mt][nt], al[mt], bh[nt]);
                }
        }

        int rbase = t * TILE_M + warp_m * 32 + (lane >> 2);
        int cbase = warp_n * 32 + 2 * (lane & 3);
        #pragma unroll
        for (int mt = 0; mt < 2; mt++) {
            #pragma unroll
            for (int nt = 0; nt < 4; nt++) {
                int r0 = rbase + mt * 16;
                int c = cbase + nt * 8;
                if (r0 < nrows)
                    *(float2*)&g_h[(size_t)r0 * D + c] = make_float2(acc[mt][nt][0], acc[mt][nt][1]);
                if (r0 + 8 < nrows)
                    *(float2*)&g_h[(size_t)(r0 + 8) * D + c] = make_float2(acc[mt][nt][2], acc[mt][nt][3]);
            }
        }
    }
}

// ---------------- CSR build (4-way MLP on the atomic chains) ----------------
__global__ void __launch_bounds__(256) k4a_hist(const int* __restrict__ ei, int E) {
    int base = blockIdx.x * 1024 + threadIdx.x;
    #pragma unroll
    for (int j = 0; j < 4; j++) {
        int e = base + j * 256;
        if (e < E) atomicAdd(&g_deg[ei[e]], 1);
    }
}
__global__ void __launch_bounds__(256) k4b_off(int N) {
    int i = blockIdx.x * 256 + threadIdx.x;
    int lane = threadIdx.x & 31;
    int v = (i < N) ? g_deg[i] : 0;
    int incl = v;
    #pragma unroll
    for (int o = 1; o < 32; o <<= 1) {
        int t = __shfl_up_sync(0xFFFFFFFFu, incl, o);
        if (lane >= o) incl += t;
    }
    int wsum = __shfl_sync(0xFFFFFFFFu, incl, 31);
    int base = 0;
    if (lane == 0) base = atomicAdd(&g_total, wsum);
    base = __shfl_sync(0xFFFFFFFFu, base, 0);
    if (i < N) {
        int off = base + incl - v;
        g_off[i] = off;
        g_cur[i] = off;
    }
}
__global__ void __launch_bounds__(256) k4c_fill(const int* __restrict__ ei,
                                                const float* __restrict__ ew, int E) {
    int base = blockIdx.x * 1024 + threadIdx.x;
    int e0 = base, e1 = base + 256, e2 = base + 512, e3 = base + 768;
    int r0 = (e0 < E) ? ei[e0] : -1;
    int r1 = (e1 < E) ? ei[e1] : -1;
    int r2 = (e2 < E) ? ei[e2] : -1;
    int r3 = (e3 < E) ? ei[e3] : -1;
    int p0 = (r0 >= 0) ? atomicAdd(&g_cur[r0], 1) : 0;
    int p1 = (r1 >= 0) ? atomicAdd(&g_cur[r1], 1) : 0;
    int p2 = (r2 >= 0) ? atomicAdd(&g_cur[r2], 1) : 0;
    int p3 = (r3 >= 0) ? atomicAdd(&g_cur[r3], 1) : 0;
    if (r0 >= 0) { g_ecol[p0] = ei[E + e0]; g_ewt[p0] = ew[e0]; }
    if (r1 >= 0) { g_ecol[p1] = ei[E + e1]; g_ewt[p1] = ew[e1]; }
    if (r2 >= 0) { g_ecol[p2] = ei[E + e2]; g_ewt[p2] = ew[e2]; }
    if (r3 >= 0) { g_ecol[p3] = ei[E + e3]; g_ewt[p3] = ew[e3]; }
}

// ---------------- k5: per-node gather aggregate + h*h ----------------
__global__ void __launch_bounds__(256) k5_agg(float* __restrict__ out, int N) {
    int n = blockIdx.x * 8 + (threadIdx.x >> 5);
    if (n >= N) return;
    int lane = threadIdx.x & 31;
    int s = g_off[n];
    int e = s + g_deg[n];
    const float4* h4 = (const float4*)g_h;
    float4 acc = {0.f, 0.f, 0.f, 0.f};
    int j = s;
    for (; j + 2 <= e; j += 2) {
        int c0 = __ldg(&g_ecol[j]), c1 = __ldg(&g_ecol[j + 1]);
        float w0 = __ldg(&g_ewt[j]), w1 = __ldg(&g_ewt[j + 1]);
        float4 v0 = h4[(size_t)c0 * 32 + lane];
        float4 v1 = h4[(size_t)c1 * 32 + lane];
        acc.x = fmaf(w0, v0.x, acc.x); acc.y = fmaf(w0, v0.y, acc.y);
        acc.z = fmaf(w0, v0.z, acc.z); acc.w = fmaf(w0, v0.w, acc.w);
        acc.x = fmaf(w1, v1.x, acc.x); acc.y = fmaf(w1, v1.y, acc.y);
        acc.z = fmaf(w1, v1.z, acc.z); acc.w = fmaf(w1, v1.w, acc.w);
    }
    if (j < e) {
        int c0 = __ldg(&g_ecol[j]);
        float w0 = __ldg(&g_ewt[j]);
        float4 v0 = h4[(size_t)c0 * 32 + lane];
        acc.x = fmaf(w0, v0.x, acc.x); acc.y = fmaf(w0, v0.y, acc.y);
        acc.z = fmaf(w0, v0.z, acc.z); acc.w = fmaf(w0, v0.w, acc.w);
    }
    float4 hv = h4[(size_t)n * 32 + lane];
    float4 o;
    o.x = fmaf(hv.x, hv.x, acc.x);
    o.y = fmaf(hv.y, hv.y, acc.y);
    o.z = fmaf(hv.z, hv.z, acc.z);
    o.w = fmaf(hv.w, hv.w, acc.w);
    __stcs(&((float4*)out)[(size_t)n * 32 + lane], o);
}

// ---------------- launch: fork CSR chain onto a side stream ----------------
extern "C" void kernel_launch(void* const* d_in, const int* in_sizes, int n_in,
                              void* d_out, int out_size) {
    const float* n_feat = (const float*)d_in[0];
    const int*   ei     = (const int*)d_in[1];
    const float* ew     = (const float*)d_in[2];
    const float* gamma  = (const float*)d_in[3];
    const float* beta   = (const float*)d_in[4];
    const float* W      = (const float*)d_in[5];
    float* out = (float*)d_out;

    int N = in_sizes[0] / D;
    int E = in_sizes[2];
    int ntiles = (N + TILE_M - 1) / TILE_M;

    cudaStream_t s2;
    cudaStreamCreateWithFlags(&s2, cudaStreamNonBlocking);
    cudaEvent_t ev_fork, ev_join;
    cudaEventCreateWithFlags(&ev_fork, cudaEventDisableTiming);
    cudaEventCreateWithFlags(&ev_join, cudaEventDisableTiming);

    // main stream: prep (feeds both branches)
    k0_prep<<<NB256, 256>>>(W);
    cudaEventRecord(ev_fork, 0);

    // side stream: CSR build chain
    cudaStreamWaitEvent(s2, ev_fork, 0);
    k4a_hist<<<(E + 1023) / 1024, 256, 0, s2>>>(ei, E);
    k4b_off<<<(N + 255) / 256, 256, 0, s2>>>(N);
    k4c_fill<<<(E + 1023) / 1024, 256, 0, s2>>>(ei, ew, E);
    cudaEventRecord(ev_join, s2);

    // main stream: BN stats -> affine -> GEMM
    k1_stats<<<264, 256>>>((const float4*)n_feat, N);
    k2_final<<<1, D>>>(gamma, beta, 1.0f / (float)N);
    cudaFuncSetAttribute(k3_mma, cudaFuncAttributeMaxDynamicSharedMemorySize, SM_TOTAL);
    k3_mma<<<296, 256, SM_TOTAL>>>(n_feat, N, ntiles);

    // join: k5 needs both g_h (main) and CSR (side)
    cudaStreamWaitEvent(0, ev_join, 0);
    k5_agg<<<(N + 7) / 8, 256>>>(out, N);

    cudaEventDestroy(ev_fork);
    cudaEventDestroy(ev_join);
    cudaStreamDestroy(s2);
}

// round 7
// speedup vs baseline: 1.5737x; 1.0581x over previous
#include <cuda_runtime.h>
#include <cuda_bf16.h>
#include <cstdint>

#define D 128
#define MAXN 100000
#define MAXE 400000
#define TILE_M 64
#define NB256 391            // (MAXN+255)/256

// ---------------- scratch (allocation-free: device globals) ----------------
__device__ float g_stats[2 * D];                    // col sums / sumsq
__device__ float g_ab[2 * D];                       // BN affine a / b
__device__ unsigned short g_Whi[D * 136];           // bf16 hi, padded [n][k] stride 136
__device__ unsigned short g_Wlo[D * 136];           // bf16 lo
__device__ float g_h[(size_t)MAXN * D];             // h (51.2 MB)
__device__ int   g_deg[MAXN];
__device__ int   g_off[MAXN];
__device__ int   g_cur[MAXN];
__device__ int   g_total;
__device__ int   g_ecol[MAXE];
__device__ float g_ewt[MAXE];

// ---------------- helpers ----------------
__device__ __forceinline__ uint32_t smem_u32(const void* p) {
    uint32_t a;
    asm("{ .reg .u64 t; cvta.to.shared.u64 t, %1; cvt.u32.u64 %0, t; }" : "=r"(a) : "l"(p));
    return a;
}
__device__ __forceinline__ void ldmx4(uint32_t addr, uint32_t r[4]) {
    asm volatile("ldmatrix.sync.aligned.m8n8.x4.shared.b16 {%0,%1,%2,%3}, [%4];"
                 : "=r"(r[0]), "=r"(r[1]), "=r"(r[2]), "=r"(r[3]) : "r"(addr));
}
__device__ __forceinline__ void mma16816(float c[4], const uint32_t a[4], const uint32_t b[2]) {
    asm volatile("mma.sync.aligned.m16n8k16.row.col.f32.bf16.bf16.f32 "
                 "{%0,%1,%2,%3}, {%4,%5,%6,%7}, {%8,%9}, {%0,%1,%2,%3};"
                 : "+f"(c[0]), "+f"(c[1]), "+f"(c[2]), "+f"(c[3])
                 : "r"(a[0]), "r"(a[1]), "r"(a[2]), "r"(a[3]), "r"(b[0]), "r"(b[1]));
}
__device__ __forceinline__ uint32_t pkbf2(float x, float y) {
    __nv_bfloat162 t = __floats2bfloat162_rn(x, y);
    return *(uint32_t*)&t;
}

// ---------------- k0a: zero CSR + stats scratch (unblocks side branch) ----------------
__global__ void k0a_zero() {
    int i = blockIdx.x * 256 + threadIdx.x;
    if (i == 0) g_total = 0;
    if (i < 2 * D) g_stats[i] = 0.0f;
    if (i < MAXN) g_deg[i] = 0;
}
// ---------------- k0b: build padded W bf16 hi/lo ----------------
__global__ void k0b_wprep(const float* __restrict__ W) {
    int i = blockIdx.x * 256 + threadIdx.x;
    if (i < D * D) {
        int n = i >> 7, k = i & 127;
        float w = W[i];
        __nv_bfloat16 hi = __float2bfloat16(w);
        float lf = w - __bfloat162float(hi);
        g_Whi[n * 136 + k] = __bfloat16_as_ushort(hi);
        g_Wlo[n * 136 + k] = __bfloat16_as_ushort(__float2bfloat16(lf));
    }
}

// ---------------- k1: column sums / sumsq ----------------
__global__ void __launch_bounds__(256) k1_stats(const float4* __restrict__ x4, int nrows) {
    int tx = threadIdx.x & 31, ty = threadIdx.x >> 5;
    float4 s = {0.f, 0.f, 0.f, 0.f}, q = {0.f, 0.f, 0.f, 0.f};
    for (int r = blockIdx.x * 8 + ty; r < nrows; r += gridDim.x * 8) {
        float4 v = x4[(size_t)r * 32 + tx];
        s.x += v.x; s.y += v.y; s.z += v.z; s.w += v.w;
        q.x += v.x * v.x; q.y += v.y * v.y; q.z += v.z * v.z; q.w += v.w * v.w;
    }
    __shared__ float4 rs[8][32], rq[8][32];
    rs[ty][tx] = s; rq[ty][tx] = q;
    __syncthreads();
    if (ty == 0) {
        for (int w = 1; w < 8; w++) {
            float4 a = rs[w][tx], b = rq[w][tx];
            s.x += a.x; s.y += a.y; s.z += a.z; s.w += a.w;
            q.x += b.x; q.y += b.y; q.z += b.z; q.w += b.w;
        }
        atomicAdd(&g_stats[4 * tx + 0], s.x);
        atomicAdd(&g_stats[4 * tx + 1], s.y);
        atomicAdd(&g_stats[4 * tx + 2], s.z);
        atomicAdd(&g_stats[4 * tx + 3], s.w);
        atomicAdd(&g_stats[D + 4 * tx + 0], q.x);
        atomicAdd(&g_stats[D + 4 * tx + 1], q.y);
        atomicAdd(&g_stats[D + 4 * tx + 2], q.z);
        atomicAdd(&g_stats[D + 4 * tx + 3], q.w);
    }
}

// ---------------- k2: finalize BN affine ----------------
__global__ void k2_final(const float* __restrict__ gamma, const float* __restrict__ beta, float inv_n) {
    int c = threadIdx.x;
    float mu  = g_stats[c] * inv_n;
    float var = fmaxf(g_stats[D + c] * inv_n - mu * mu, 0.0f);
    float a = gamma[c] * rsqrtf(var + 1e-5f);
    g_ab[c] = a;
    g_ab[D + c] = beta[c] - mu * a;
}

// ---------------- k3: HMMA bf16 2-split GEMM + register prefetch ----------------
#define SM_WHI 0
#define SM_WLO 34816
#define SM_XHI 69632
#define SM_XLO 87040
#define SM_TOTAL 104448
#define XSTR 272     // row stride bytes

__global__ void __launch_bounds__(256, 2) k3_mma(const float* __restrict__ x,
                                                 int nrows, int ntiles) {
    extern __shared__ __align__(16) char sm[];
    uint32_t smb = smem_u32(sm);
    int tid = threadIdx.x, wid = tid >> 5, lane = tid & 31;
    int warp_m = wid & 1;       // 2 m-blocks of 32 rows
    int warp_n = wid >> 1;      // 4 n-blocks of 32 cols

    {
        const uint4* hs = (const uint4*)g_Whi;
        const uint4* ls = (const uint4*)g_Wlo;
        uint4* hd = (uint4*)(sm + SM_WHI);
        uint4* ld = (uint4*)(sm + SM_WLO);
        for (int i = tid; i < 2176; i += 256) { hd[i] = hs[i]; ld[i] = ls[i]; }
    }

    int laneRowA = (lane & 7) + ((lane >> 3) & 1) * 8;
    int laneKA   = (lane >> 4) * 8;
    int laneRowB = (lane & 7) + ((lane >> 4) & 1) * 8;
    int laneKB   = ((lane >> 3) & 1) * 8;
    uint32_t aoff = (uint32_t)((warp_m * 32 + laneRowA) * XSTR + laneKA * 2);
    uint32_t boff = (uint32_t)((warp_n * 32 + laneRowB) * XSTR + laneKB * 2);
    uint32_t a_hi = smb + SM_XHI + aoff, a_lo = smb + SM_XLO + aoff;
    uint32_t b_hi = smb + SM_WHI + boff, b_lo = smb + SM_WLO + boff;

    const float4* x4 = (const float4*)x;
    const float4* ab4 = (const float4*)g_ab;
    int row_in = tid >> 5;            // staging: each thread owns rows {row_in + 8j}, quad cq
    int cq = tid & 31;

    // prefetch first tile into regs
    float4 v[8];
    {
        int t0 = blockIdx.x;
        #pragma unroll
        for (int it = 0; it < 8; it++) {
            int gr = t0 * TILE_M + row_in + it * 8;
            v[it] = (t0 < ntiles && gr < nrows) ? x4[(size_t)gr * 32 + cq]
                                                : make_float4(0.f, 0.f, 0.f, 0.f);
        }
    }

    for (int t = blockIdx.x; t < ntiles; t += gridDim.x) {
        // ---- convert regs -> bf16 hi/lo -> STS ----
        #pragma unroll
        for (int it = 0; it < 8; it++) {
            int r = row_in + it * 8;
            float4 a = __ldg(&ab4[cq]), b = __ldg(&ab4[32 + cq]);
            float y0 = fmaxf(fmaf(a.x, v[it].x, b.x), 0.f);
            float y1 = fmaxf(fmaf(a.y, v[it].y, b.y), 0.f);
            float y2 = fmaxf(fmaf(a.z, v[it].z, b.z), 0.f);
            float y3 = fmaxf(fmaf(a.w, v[it].w, b.w), 0.f);
            __nv_bfloat16 h0 = __float2bfloat16(y0), h1 = __float2bfloat16(y1);
            __nv_bfloat16 h2 = __float2bfloat16(y2), h3 = __float2bfloat16(y3);
            uint2 hiw, low;
            hiw.x = (uint32_t)__bfloat16_as_ushort(h0) | ((uint32_t)__bfloat16_as_ushort(h1) << 16);
            hiw.y = (uint32_t)__bfloat16_as_ushort(h2) | ((uint32_t)__bfloat16_as_ushort(h3) << 16);
            low.x = pkbf2(y0 - __bfloat162float(h0), y1 - __bfloat162float(h1));
            low.y = pkbf2(y2 - __bfloat162float(h2), y3 - __bfloat162float(h3));
            uint32_t off = (uint32_t)(r * XSTR + cq * 8);
            *(uint2*)(sm + SM_XHI + off) = hiw;
            *(uint2*)(sm + SM_XLO + off) = low;
        }
        __syncthreads();

        // ---- issue prefetch of next tile (latency hides under MMAs) ----
        {
            int tn = t + gridDim.x;
            #pragma unroll
            for (int it = 0; it < 8; it++) {
                int gr = tn * TILE_M + row_in + it * 8;
                if (tn < ntiles && gr < nrows) v[it] = x4[(size_t)gr * 32 + cq];
                else v[it] = make_float4(0.f, 0.f, 0.f, 0.f);
            }
        }

        // ---- mainloop: 8 k16-steps x 3 products ----
        float acc[2][4][4];
        #pragma unroll
        for (int mt = 0; mt < 2; mt++)
            #pragma unroll
            for (int nt = 0; nt < 4; nt++)
                #pragma unroll
                for (int j = 0; j < 4; j++) acc[mt][nt][j] = 0.f;

        for (int ko = 0; ko < 8; ko++) {
            uint32_t kb = ko * 32;
            uint32_t ah[2][4], al[2][4];
            #pragma unroll
            for (int mt = 0; mt < 2; mt++) {
                ldmx4(a_hi + mt * (16 * XSTR) + kb, ah[mt]);
                ldmx4(a_lo + mt * (16 * XSTR) + kb, al[mt]);
            }
            uint32_t bh[4][2], bl[4][2];
            #pragma unroll
            for (int np = 0; np < 2; np++) {
                uint32_t tm[4];
                ldmx4(b_hi + np * (16 * XSTR) + kb, tm);
                bh[2*np][0] = tm[0]; bh[2*np][1] = tm[1];
                bh[2*np+1][0] = tm[2]; bh[2*np+1][1] = tm[3];
                ldmx4(b_lo + np * (16 * XSTR) + kb, tm);
                bl[2*np][0] = tm[0]; bl[2*np][1] = tm[1];
                bl[2*np+1][0] = tm[2]; bl[2*np+1][1] = tm[3];
            }
            #pragma unroll
            for (int mt = 0; mt < 2; mt++)
                #pragma unroll
                for (int nt = 0; nt < 4; nt++) {
                    mma16816(acc[mt][nt], ah[mt], bh[nt]);
                    mma16816(acc[mt][nt], ah[mt], bl[nt]);
                    mma16816(acc[mt][nt], al[mt], bh[nt]);
                }
        }

        // ---- epilogue: write h ----
        int rbase = t * TILE_M + warp_m * 32 + (lane >> 2);
        int cbase = warp_n * 32 + 2 * (lane & 3);
        #pragma unroll
        for (int mt = 0; mt < 2; mt++) {
            #pragma unroll
            for (int nt = 0; nt < 4; nt++) {
                int r0 = rbase + mt * 16;
                int c = cbase + nt * 8;
                if (r0 < nrows)
                    *(float2*)&g_h[(size_t)r0 * D + c] = make_float2(acc[mt][nt][0], acc[mt][nt][1]);
                if (r0 + 8 < nrows)
                    *(float2*)&g_h[(size_t)(r0 + 8) * D + c] = make_float2(acc[mt][nt][2], acc[mt][nt][3]);
            }
        }
        __syncthreads();
    }
}

// ---------------- CSR build ----------------
__global__ void __launch_bounds__(256) k4a_hist(const int* __restrict__ ei, int E) {
    int base = blockIdx.x * 1024 + threadIdx.x;
    #pragma unroll
    for (int j = 0; j < 4; j++) {
        int e = base + j * 256;
        if (e < E) atomicAdd(&g_deg[ei[e]], 1);
    }
}
__global__ void __launch_bounds__(256) k4b_off(int N) {
    int i = blockIdx.x * 256 + threadIdx.x;
    int lane = threadIdx.x & 31;
    int v = (i < N) ? g_deg[i] : 0;
    int incl = v;
    #pragma unroll
    for (int o = 1; o < 32; o <<= 1) {
        int t = __shfl_up_sync(0xFFFFFFFFu, incl, o);
        if (lane >= o) incl += t;
    }
    int wsum = __shfl_sync(0xFFFFFFFFu, incl, 31);
    int base = 0;
    if (lane == 0) base = atomicAdd(&g_total, wsum);
    base = __shfl_sync(0xFFFFFFFFu, base, 0);
    if (i < N) {
        int off = base + incl - v;
        g_off[i] = off;
        g_cur[i] = off;
    }
}
__global__ void __launch_bounds__(256) k4c_fill(const int* __restrict__ ei,
                                                const float* __restrict__ ew, int E) {
    int base = blockIdx.x * 1024 + threadIdx.x;
    int e0 = base, e1 = base + 256, e2 = base + 512, e3 = base + 768;
    int r0 = (e0 < E) ? ei[e0] : -1;
    int r1 = (e1 < E) ? ei[e1] : -1;
    int r2 = (e2 < E) ? ei[e2] : -1;
    int r3 = (e3 < E) ? ei[e3] : -1;
    int p0 = (r0 >= 0) ? atomicAdd(&g_cur[r0], 1) : 0;
    int p1 = (r1 >= 0) ? atomicAdd(&g_cur[r1], 1) : 0;
    int p2 = (r2 >= 0) ? atomicAdd(&g_cur[r2], 1) : 0;
    int p3 = (r3 >= 0) ? atomicAdd(&g_cur[r3], 1) : 0;
    if (r0 >= 0) { g_ecol[p0] = ei[E + e0]; g_ewt[p0] = ew[e0]; }
    if (r1 >= 0) { g_ecol[p1] = ei[E + e1]; g_ewt[p1] = ew[e1]; }
    if (r2 >= 0) { g_ecol[p2] = ei[E + e2]; g_ewt[p2] = ew[e2]; }
    if (r3 >= 0) { g_ecol[p3] = ei[E + e3]; g_ewt[p3] = ew[e3]; }
}

// ---------------- k5: per-node gather aggregate + h*h (MLP-4) ----------------
__global__ void __launch_bounds__(256) k5_agg(float* __restrict__ out, int N) {
    int n = blockIdx.x * 8 + (threadIdx.x >> 5);
    if (n >= N) return;
    int lane = threadIdx.x & 31;
    int s = g_off[n];
    int e = s + g_deg[n];
    const float4* h4 = (const float4*)g_h;
    float4 acc = {0.f, 0.f, 0.f, 0.f};
    int j = s;
    for (; j + 4 <= e; j += 4) {
        int c0 = __ldg(&g_ecol[j]),     c1 = __ldg(&g_ecol[j + 1]);
        int c2 = __ldg(&g_ecol[j + 2]), c3 = __ldg(&g_ecol[j + 3]);
        float w0 = __ldg(&g_ewt[j]),     w1 = __ldg(&g_ewt[j + 1]);
        float w2 = __ldg(&g_ewt[j + 2]), w3 = __ldg(&g_ewt[j + 3]);
        float4 v0 = h4[(size_t)c0 * 32 + lane];
        float4 v1 = h4[(size_t)c1 * 32 + lane];
        float4 v2 = h4[(size_t)c2 * 32 + lane];
        float4 v3 = h4[(size_t)c3 * 32 + lane];
        acc.x = fmaf(w0, v0.x, acc.x); acc.y = fmaf(w0, v0.y, acc.y);
        acc.z = fmaf(w0, v0.z, acc.z); acc.w = fmaf(w0, v0.w, acc.w);
        acc.x = fmaf(w1, v1.x, acc.x); acc.y = fmaf(w1, v1.y, acc.y);
        acc.z = fmaf(w1, v1.z, acc.z); acc.w = fmaf(w1, v1.w, acc.w);
        acc.x = fmaf(w2, v2.x, acc.x); acc.y = fmaf(w2, v2.y, acc.y);
        acc.z = fmaf(w2, v2.z, acc.z); acc.w = fmaf(w2, v2.w, acc.w);
        acc.x = fmaf(w3, v3.x, acc.x); acc.y = fmaf(w3, v3.y, acc.y);
        acc.z = fmaf(w3, v3.z, acc.z); acc.w = fmaf(w3, v3.w, acc.w);
    }
    for (; j < e; j++) {
        int c0 = __ldg(&g_ecol[j]);
        float w0 = __ldg(&g_ewt[j]);
        float4 v0 = h4[(size_t)c0 * 32 + lane];
        acc.x = fmaf(w0, v0.x, acc.x); acc.y = fmaf(w0, v0.y, acc.y);
        acc.z = fmaf(w0, v0.z, acc.z); acc.w = fmaf(w0, v0.w, acc.w);
    }
    float4 hv = h4[(size_t)n * 32 + lane];
    float4 o;
    o.x = fmaf(hv.x, hv.x, acc.x);
    o.y = fmaf(hv.y, hv.y, acc.y);
    o.z = fmaf(hv.z, hv.z, acc.z);
    o.w = fmaf(hv.w, hv.w, acc.w);
    __stcs(&((float4*)out)[(size_t)n * 32 + lane], o);
}

// ---------------- launch: fork CSR chain onto a side stream ----------------
extern "C" void kernel_launch(void* const* d_in, const int* in_sizes, int n_in,
                              void* d_out, int out_size) {
    const float* n_feat = (const float*)d_in[0];
    const int*   ei     = (const int*)d_in[1];
    const float* ew     = (const float*)d_in[2];
    const float* gamma  = (const float*)d_in[3];
    const float* beta   = (const float*)d_in[4];
    const float* W      = (const float*)d_in[5];
    float* out = (float*)d_out;

    int N = in_sizes[0] / D;
    int E = in_sizes[2];
    int ntiles = (N + TILE_M - 1) / TILE_M;

    cudaStream_t s2;
    cudaStreamCreateWithFlags(&s2, cudaStreamNonBlocking);
    cudaEvent_t ev_fork, ev_join;
    cudaEventCreateWithFlags(&ev_fork, cudaEventDisableTiming);
    cudaEventCreateWithFlags(&ev_join, cudaEventDisableTiming);

    // main: zero scratch (unblocks both branches)
    k0a_zero<<<NB256, 256>>>();
    cudaEventRecord(ev_fork, 0);

    // side stream: CSR build chain
    cudaStreamWaitEvent(s2, ev_fork, 0);
    k4a_hist<<<(E + 1023) / 1024, 256, 0, s2>>>(ei, E);
    k4b_off<<<(N + 255) / 256, 256, 0, s2>>>(N);
    k4c_fill<<<(E + 1023) / 1024, 256, 0, s2>>>(ei, ew, E);
    cudaEventRecord(ev_join, s2);

    // main stream: W prep -> BN stats -> affine -> GEMM
    k0b_wprep<<<64, 256>>>(W);
    k1_stats<<<264, 256>>>((const float4*)n_feat, N);
    k2_final<<<1, D>>>(gamma, beta, 1.0f / (float)N);
    cudaFuncSetAttribute(k3_mma, cudaFuncAttributeMaxDynamicSharedMemorySize, SM_TOTAL);
    k3_mma<<<296, 256, SM_TOTAL>>>(n_feat, N, ntiles);

    // join: k5 needs both g_h (main) and CSR (side)
    cudaStreamWaitEvent(0, ev_join, 0);
    k5_agg<<<(N + 7) / 8, 256>>>(out, N);

    cudaEventDestroy(ev_fork);
    cudaEventDestroy(ev_join);
    cudaStreamDestroy(s2);
}